// round 16
// baseline (speedup 1.0000x reference)
#include <cuda_runtime.h>
#include <cstdint>

// ---------------------------------------------------------------------------
// SemanticLSTM: 79-step LSTM with semantic gating and greedy argmax feedback.
// All math fp32 (argmax feedback makes low precision catastrophic).
//
// Per step (graph nodes):
//   k_uw   : u = (Wa @ emb[cap]) * bx ; w = (Ua @ h) * bh        [64x2048 each]
//   k_pre  : preW = Wc(g) @ u(g) ; preU = Uc(g) @ w(g)           [64x2048 each]
//   k_cell : gates -> c,h update ; reset argmax keys
//   k_out  : out = h @ W_last + b_last ; atomicMax argmax keys   [64x10000]
// ---------------------------------------------------------------------------

#define B_     64
#define T_     80
#define HID    512
#define VOCAB_ 10000
#define NSTEPS 79

#define BM   64
#define BN   32
#define BK   32
#define ASTR 68   // padded smem stride for A (68*4B = 272B, 16B aligned per row)

// ------------------------------- scratch ----------------------------------
__device__ __align__(16) float g_bx[B_ * 2048];
__device__ __align__(16) float g_bh[B_ * 2048];
__device__ __align__(16) float g_bv[B_ * 2048];
__device__ __align__(16) float g_av[B_ * 2048];
__device__ __align__(16) float g_preBase[B_ * 2048];
__device__ __align__(16) float g_u[B_ * 2048];
__device__ __align__(16) float g_w[B_ * 2048];
__device__ __align__(16) float g_preW[B_ * 2048];
__device__ __align__(16) float g_preU[B_ * 2048];
__device__ __align__(16) float g_h[B_ * HID];
__device__ __align__(16) float g_c[B_ * HID];
__device__ unsigned long long g_amax[B_];

// float -> order-preserving uint (max of keys == argmax of floats)
__device__ __forceinline__ unsigned fordu(float f) {
    unsigned u = __float_as_uint(f);
    return (u & 0x80000000u) ? ~u : (u | 0x80000000u);
}
__device__ __forceinline__ unsigned long long kmax64(unsigned long long a,
                                                     unsigned long long b) {
    return a > b ? a : b;
}

// ---------------------------------------------------------------------------
// Register-tiled fp32 GEMM core: C tile = 64 (all rows) x 32 cols, K-blocked
// by 32. 128 threads, 16 accumulators/thread (4 rows x 4 cols), float4 smem.
// A is [64 x K] (per-thread row pointer Arow, element k at Arow[k]).
// W element (k, j) at Wp[k*wld + j].
// KG: predicate k < K (for K=300). NG: predicate cols < nValid (VOCAB tail).
// ---------------------------------------------------------------------------
template <bool KG, bool NG>
__device__ __forceinline__ void mm_core(const float* __restrict__ Arow,
                                        const float* __restrict__ AmulRow,
                                        const float* __restrict__ Wp, int wld,
                                        int K, int nValid, float acc[4][4]) {
    __shared__ float As[BK][ASTR];   // [k][m] transposed
    __shared__ float Bs[BK][BN];

    const int tid  = threadIdx.x;
    const int mld  = tid & 63;           // A-load row
    const int kq   = (tid >> 6) << 4;    // A-load k offset: 0 or 16
    const int row0 = (tid >> 3) << 2;    // compute rows [row0, row0+4)
    const int col0 = (tid & 7) << 2;     // compute cols [col0, col0+4)

    for (int kb = 0; kb < K; kb += BK) {
        // --- load A tile 64x32 (transposed into smem) ---
#pragma unroll
        for (int c = 0; c < 4; c++) {
            int k = kb + kq + 4 * c;
            float4 a = make_float4(0.f, 0.f, 0.f, 0.f);
            if (!KG || k < K) {
                a = *(const float4*)(Arow + k);
                if (AmulRow) {
                    float4 mm = *(const float4*)(AmulRow + k);
                    a.x *= mm.x; a.y *= mm.y; a.z *= mm.z; a.w *= mm.w;
                }
            }
            As[kq + 4 * c + 0][mld] = a.x;
            As[kq + 4 * c + 1][mld] = a.y;
            As[kq + 4 * c + 2][mld] = a.z;
            As[kq + 4 * c + 3][mld] = a.w;
        }
        // --- load B tile 32x32 ---
#pragma unroll
        for (int r = 0; r < 2; r++) {
            int idx = tid + r * 128;
            int kk  = idx >> 3;
            int j4  = (idx & 7) << 2;
            float4 b = make_float4(0.f, 0.f, 0.f, 0.f);
            bool ok = true;
            if (KG && (kb + kk) >= K) ok = false;
            if (NG && (j4 + 4) > nValid) ok = false;
            if (ok) b = *(const float4*)(Wp + (size_t)(kb + kk) * wld + j4);
            *(float4*)&Bs[kk][j4] = b;
        }
        __syncthreads();
#pragma unroll
        for (int kk = 0; kk < BK; kk++) {
            float4 a = *(const float4*)&As[kk][row0];
            float4 b = *(const float4*)&Bs[kk][col0];
            acc[0][0] = fmaf(a.x, b.x, acc[0][0]);
            acc[0][1] = fmaf(a.x, b.y, acc[0][1]);
            acc[0][2] = fmaf(a.x, b.z, acc[0][2]);
            acc[0][3] = fmaf(a.x, b.w, acc[0][3]);
            acc[1][0] = fmaf(a.y, b.x, acc[1][0]);
            acc[1][1] = fmaf(a.y, b.y, acc[1][1]);
            acc[1][2] = fmaf(a.y, b.z, acc[1][2]);
            acc[1][3] = fmaf(a.y, b.w, acc[1][3]);
            acc[2][0] = fmaf(a.z, b.x, acc[2][0]);
            acc[2][1] = fmaf(a.z, b.y, acc[2][1]);
            acc[2][2] = fmaf(a.z, b.z, acc[2][2]);
            acc[2][3] = fmaf(a.z, b.w, acc[2][3]);
            acc[3][0] = fmaf(a.w, b.x, acc[3][0]);
            acc[3][1] = fmaf(a.w, b.y, acc[3][1]);
            acc[3][2] = fmaf(a.w, b.z, acc[3][2]);
            acc[3][3] = fmaf(a.w, b.w, acc[3][3]);
        }
        __syncthreads();
    }
}

// ---------------------------------------------------------------------------
// k_init: zero h, c; seed argmax keys with captions[:,0]
// ---------------------------------------------------------------------------
__global__ void k_init(const int* __restrict__ captions) {
    int i = blockIdx.x * blockDim.x + threadIdx.x;
    if (i < B_ * HID) {
        g_h[i] = 0.f;
        g_c[i] = 0.f;
    }
    if (i < B_)
        g_amax[i] =
            (unsigned long long)(0xFFFFFFFFu - (unsigned)captions[i * T_]);
}

// ---------------------------------------------------------------------------
// k_mm: precompute GEMMs  C[64,2048] = A[64,K] @ W[4,K,512]  (gate-concat N)
// outSel: 0=g_bx 1=g_bh 2=g_bv 3=g_av
// ---------------------------------------------------------------------------
__global__ void __launch_bounds__(128)
k_mm(const float* __restrict__ A, int K, const float* __restrict__ W,
     int outSel) {
    const int tid   = threadIdx.x;
    const int nBase = blockIdx.x * BN;
    const int g     = nBase >> 9;
    const int nIn   = nBase & 511;
    const float* Arow = A + (size_t)(tid & 63) * K;
    const float* Wp   = W + (size_t)g * K * 512 + nIn;
    float acc[4][4] = {};
    mm_core<true, false>(Arow, nullptr, Wp, 512, K, BN, acc);

    float* C = (outSel == 0) ? g_bx : (outSel == 1) ? g_bh
                             : (outSel == 2) ? g_bv : g_av;
    const int row0 = (tid >> 3) << 2;
    const int col0 = (tid & 7) << 2;
#pragma unroll
    for (int r = 0; r < 4; r++)
#pragma unroll
        for (int c = 0; c < 4; c++)
            C[(size_t)(row0 + r) * 2048 + nBase + col0 + c] = acc[r][c];
}

// ---------------------------------------------------------------------------
// k_uw: y=0: u = (Wa @ embed[cap]) * bx ; y=1: w = (Ua @ h) * bh
// cap decoded from g_amax keys (seeded/updated by k_init / k_out).
// ---------------------------------------------------------------------------
__global__ void __launch_bounds__(128)
k_uw(const float* __restrict__ embed, const float* __restrict__ Wa,
     const float* __restrict__ Ua) {
    const int tid   = threadIdx.x;
    const int nBase = blockIdx.x * BN;
    const int g     = nBase >> 9;
    const int nIn   = nBase & 511;
    const int path  = blockIdx.y;
    const int mld   = tid & 63;

    const float* Arow;
    const float* Wp;
    if (path == 0) {
        unsigned cap = 0xFFFFFFFFu - (unsigned)g_amax[mld];
        Arow = embed + (size_t)cap * 512;
        Wp   = Wa + (size_t)g * (512 * 512) + nIn;
    } else {
        Arow = g_h + (size_t)mld * 512;
        Wp   = Ua + (size_t)g * (512 * 512) + nIn;
    }
    float acc[4][4] = {};
    mm_core<false, false>(Arow, nullptr, Wp, 512, 512, BN, acc);

    const float* emul = (path == 0) ? g_bx : g_bh;
    float* C          = (path == 0) ? g_u : g_w;
    const int row0 = (tid >> 3) << 2;
    const int col0 = (tid & 7) << 2;
#pragma unroll
    for (int r = 0; r < 4; r++)
#pragma unroll
        for (int c = 0; c < 4; c++) {
            size_t o = (size_t)(row0 + r) * 2048 + nBase + col0 + c;
            C[o] = acc[r][c] * emul[o];
        }
}

// ---------------------------------------------------------------------------
// k_pre: block-diagonal per-gate GEMM.
// mode 0 (grid.y=2): preW = Wc(g) @ u(g) ; preU = Uc(g) @ w(g)
// mode 1 (grid.y=1): preBase = Cc(g) @ (av*bv)(g) + bias    (one-time)
// ---------------------------------------------------------------------------
__global__ void __launch_bounds__(128)
k_pre(const float* __restrict__ W0, const float* __restrict__ W1,
      const float* __restrict__ biasv, int mode) {
    const int tid   = threadIdx.x;
    const int nBase = blockIdx.x * BN;
    const int g     = nBase >> 9;
    const int nIn   = nBase & 511;
    const int path  = blockIdx.y;
    const int mld   = tid & 63;

    const float* A;
    const float* am = nullptr;
    const float* W;
    const float* ab = nullptr;
    float* C;
    if (mode == 0) {
        if (path == 0) { A = g_u; W = W0; C = g_preW; }
        else           { A = g_w; W = W1; C = g_preU; }
    } else {
        A = g_av; am = g_bv; W = W0; ab = biasv; C = g_preBase;
    }

    const float* Arow  = A + (size_t)mld * 2048 + g * 512;
    const float* AmRow = am ? am + (size_t)mld * 2048 + g * 512 : nullptr;
    const float* Wp    = W + (size_t)g * (512 * 512) + nIn;
    float acc[4][4] = {};
    mm_core<false, false>(Arow, AmRow, Wp, 512, 512, BN, acc);

    const int row0 = (tid >> 3) << 2;
    const int col0 = (tid & 7) << 2;
#pragma unroll
    for (int r = 0; r < 4; r++)
#pragma unroll
        for (int c = 0; c < 4; c++) {
            float v = acc[r][c];
            if (ab) v += ab[nBase + col0 + c];
            C[(size_t)(row0 + r) * 2048 + nBase + col0 + c] = v;
        }
}

// ---------------------------------------------------------------------------
// k_cell: LSTM cell update + reset argmax keys. 64 blocks x 512 threads.
// ---------------------------------------------------------------------------
__global__ void k_cell() {
    int b  = blockIdx.x;
    int hh = threadIdx.x;
    int base = b * 2048;
    float pi = g_preW[base + hh]        + g_preU[base + hh]        + g_preBase[base + hh];
    float pf = g_preW[base + 512 + hh]  + g_preU[base + 512 + hh]  + g_preBase[base + 512 + hh];
    float po = g_preW[base + 1024 + hh] + g_preU[base + 1024 + hh] + g_preBase[base + 1024 + hh];
    float pg = g_preW[base + 1536 + hh] + g_preU[base + 1536 + hh] + g_preBase[base + 1536 + hh];
    float ig = 1.f / (1.f + expf(-pi));
    float fg = 1.f / (1.f + expf(-pf));
    float og = 1.f / (1.f + expf(-po));
    float gg = tanhf(pg);
    int idx = b * HID + hh;
    float c = fg * g_c[idx] + ig * gg;
    g_c[idx] = c;
    g_h[idx] = og * tanhf(c);
    if (hh == 0) g_amax[b] = 0ull;
}

// ---------------------------------------------------------------------------
// k_out: out = h @ W_last + b_last, store slice, argmax via atomicMax on
// (ord(value)<<32 | ~col) keys — first-index tie-break like jnp.argmax.
// ---------------------------------------------------------------------------
__global__ void __launch_bounds__(128)
k_out(const float* __restrict__ Wl, const float* __restrict__ bl,
      float* __restrict__ outp) {
    const int tid   = threadIdx.x;
    const int nBase = blockIdx.x * BN;
    int nValid = VOCAB_ - nBase;
    if (nValid > BN) nValid = BN;
    const int mld = tid & 63;
    const float* Arow = g_h + (size_t)mld * 512;
    float acc[4][4] = {};
    mm_core<false, true>(Arow, nullptr, Wl + nBase, VOCAB_, 512, nValid, acc);

    const int row0 = (tid >> 3) << 2;
    const int col0 = (tid & 7) << 2;
    __shared__ unsigned long long sk[64][8];
#pragma unroll
    for (int r = 0; r < 4; r++) {
        int m = row0 + r;
        unsigned long long best = 0ull;
#pragma unroll
        for (int c = 0; c < 4; c++) {
            int n = nBase + col0 + c;
            if (col0 + c < nValid) {
                float v = acc[r][c] + bl[n];
                outp[(size_t)m * (NSTEPS * VOCAB_) + n] = v;
                unsigned long long key =
                    ((unsigned long long)fordu(v) << 32) |
                    (unsigned long long)(0xFFFFFFFFu - (unsigned)n);
                best = kmax64(best, key);
            }
        }
        sk[m][tid & 7] = best;
    }
    __syncthreads();
    if (tid < 64) {
        unsigned long long best = sk[tid][0];
#pragma unroll
        for (int j = 1; j < 8; j++) best = kmax64(best, sk[tid][j]);
        atomicMax(&g_amax[tid], best);
    }
}

// ---------------------------------------------------------------------------
extern "C" void kernel_launch(void* const* d_in, const int* in_sizes, int n_in,
                              void* d_out, int out_size) {
    (void)in_sizes; (void)n_in; (void)out_size;
    const int*   captions = (const int*)d_in[0];
    const float* cnn      = (const float*)d_in[1];
    const float* sem      = (const float*)d_in[2];
    const float* Wa       = (const float*)d_in[3];
    const float* Wb       = (const float*)d_in[4];
    const float* Wc       = (const float*)d_in[5];
    const float* Ca       = (const float*)d_in[6];
    const float* Cb       = (const float*)d_in[7];
    const float* Cc       = (const float*)d_in[8];
    const float* Ua       = (const float*)d_in[9];
    const float* Ub       = (const float*)d_in[10];
    const float* Uc       = (const float*)d_in[11];
    const float* bias     = (const float*)d_in[12];
    const float* embed    = (const float*)d_in[13];
    const float* Wl       = (const float*)d_in[14];
    const float* bl       = (const float*)d_in[15];
    float* out = (float*)d_out;

    // init state + seed cap0
    k_init<<<128, 256>>>(captions);

    // one-time precompute: bx, bh, bv, av, preBase(=v_feat+bias)
    k_mm<<<64, 128>>>(sem, 300, Wb, 0);     // bx
    k_mm<<<64, 128>>>(sem, 300, Ub, 1);     // bh
    k_mm<<<64, 128>>>(sem, 300, Cb, 2);     // bv
    k_mm<<<64, 128>>>(cnn, 2048, Ca, 3);    // av
    k_pre<<<dim3(64, 1), 128>>>(Cc, Cc, bias, 1);  // preBase

    // recurrent steps
    for (int t = 0; t < NSTEPS; ++t) {
        k_uw<<<dim3(64, 2), 128>>>(embed, Wa, Ua);
        k_pre<<<dim3(64, 2), 128>>>(Wc, Uc, nullptr, 0);
        k_cell<<<64, 512>>>();
        k_out<<<313, 128>>>(Wl, bl, out + (size_t)t * VOCAB_);
    }
}

// round 17
// speedup vs baseline: 1.5327x; 1.5327x over previous
#include <cuda_runtime.h>
#include <cstdint>

// ---------------------------------------------------------------------------
// SemanticLSTM: 79-step LSTM with semantic gating and greedy argmax feedback.
// fp32 math (argmax feedback), but using sm_103a packed fma.rn.f32x2 (bit-
// identical to scalar fmaf per lane) + cp.async double-buffered GEMM pipeline.
// ---------------------------------------------------------------------------

#define B_     64
#define T_     80
#define VOCAB_ 10000
#define NSTEPS 79

#define NT   128     // threads per GEMM block
#define BN   32      // output cols per block
#define ACH  4       // A 16B-chunks per thread (64 rows * 8 chunks / 128 thr)

typedef unsigned long long ull;

// ------------------------------- scratch ----------------------------------
__device__ __align__(16) float g_bx[B_ * 2048];
__device__ __align__(16) float g_bh[B_ * 2048];
__device__ __align__(16) float g_bv[B_ * 2048];
__device__ __align__(16) float g_av[B_ * 2048];
__device__ __align__(16) float g_preBase[B_ * 2048];
__device__ __align__(16) float g_u[B_ * 2048];
__device__ __align__(16) float g_w[B_ * 2048];
__device__ __align__(16) float g_preW[B_ * 2048];
__device__ __align__(16) float g_preU[B_ * 2048];
__device__ __align__(16) float g_h[B_ * 512];
__device__ __align__(16) float g_c[B_ * 512];
__device__ unsigned long long g_amax[B_];

// ------------------------------- helpers ----------------------------------
__device__ __forceinline__ unsigned fordu(float f) {
    unsigned u = __float_as_uint(f);
    return (u & 0x80000000u) ? ~u : (u | 0x80000000u);
}
__device__ __forceinline__ ull kmax64(ull a, ull b) { return a > b ? a : b; }

__device__ __forceinline__ ull pack2(float x) {
    ull r;
    asm("mov.b64 %0, {%1, %1};" : "=l"(r) : "f"(x));
    return r;
}
__device__ __forceinline__ void unpack2(ull v, float& lo, float& hi) {
    asm("mov.b64 {%0, %1}, %2;" : "=f"(lo), "=f"(hi) : "l"(v));
}
// packed fp32 FMA (sm_103a): d.lo = a.lo*b.lo+c.lo ; d.hi likewise. Exact FMA.
__device__ __forceinline__ ull fma2(ull a, ull b, ull c) {
    ull d;
    asm("fma.rn.f32x2 %0, %1, %2, %3;" : "=l"(d) : "l"(a), "l"(b), "l"(c));
    return d;
}

__device__ __forceinline__ void cpa16(uint32_t s, const float* g, bool v) {
    asm volatile("cp.async.cg.shared.global [%0], [%1], 16, %2;"
                 :: "r"(s), "l"(g), "r"(v ? 16 : 0) : "memory");
}
__device__ __forceinline__ void cpa_commit() {
    asm volatile("cp.async.commit_group;" ::: "memory");
}
__device__ __forceinline__ void cpa_wait0() {
    asm volatile("cp.async.wait_group 0;" ::: "memory");
}

// ---------------------------------------------------------------------------
// Double-buffered cp.async GEMM core. C tile = 64 rows x 32 cols, BK=32.
// 128 threads, acc = 4 rows x 2 f32x2 col-pairs per thread.
// ap[i]:  per-thread A 16B-chunk base pointers (advance by kb floats)
// bp[i]:  per-thread B 16B-chunk base pointers (advance by kb*wld floats)
// KG: k < K guard (K not multiple of 32 handled if K%4==0). NG: col guard.
// ---------------------------------------------------------------------------
template <bool KG, bool NG>
__device__ __forceinline__ void mm_pipe(const float* const ap[ACH],
                                        const int kcA[ACH],
                                        const float* const bp[2],
                                        const int kkB[2], const bool bok[2],
                                        int wld, int K, ull acc[4][2]) {
    __shared__ float As[2][64][36];   // row-major A tile, 144B row pitch
    __shared__ float Bs[2][32][BN];

    const int tid = threadIdx.x;
    uint32_t as0[ACH], bs0[2];
#pragma unroll
    for (int i = 0; i < ACH; i++) {
        int c = tid + NT * i, row = c >> 3, kc = c & 7;
        as0[i] = (uint32_t)__cvta_generic_to_shared(&As[0][row][kc * 4]);
    }
#pragma unroll
    for (int i = 0; i < 2; i++) {
        int c = tid + NT * i, kk = c >> 3, jc = c & 7;
        bs0[i] = (uint32_t)__cvta_generic_to_shared(&Bs[0][kk][jc * 4]);
    }

    const int nkb = (K + 31) >> 5;
    auto issue = [&](int ib) {
        const int kb  = ib * 32;
        const uint32_t abo = (ib & 1) ? (uint32_t)(64 * 36 * 4) : 0u;
        const uint32_t bbo = (ib & 1) ? (uint32_t)(32 * BN * 4) : 0u;
#pragma unroll
        for (int i = 0; i < ACH; i++) {
            bool v = !KG || (kb + kcA[i] < K);
            cpa16(as0[i] + abo, ap[i] + kb, v);
        }
#pragma unroll
        for (int i = 0; i < 2; i++) {
            bool v = (!KG || (kb + kkB[i] < K)) && (!NG || bok[i]);
            cpa16(bs0[i] + bbo, bp[i] + (size_t)kb * wld, v);
        }
        cpa_commit();
    };

    issue(0);
    const int row0 = (tid >> 3) << 2;
    const int col0 = (tid & 7) << 2;

    for (int ib = 0; ib < nkb; ib++) {
        cpa_wait0();
        __syncthreads();          // tiles for ib visible; everyone done ib-1
        if (ib + 1 < nkb) issue(ib + 1);
        const int cur = ib & 1;
#pragma unroll
        for (int k4 = 0; k4 < 8; k4++) {
            float4 a4[4];
#pragma unroll
            for (int r = 0; r < 4; r++)
                a4[r] = *(const float4*)&As[cur][row0 + r][k4 * 4];
#pragma unroll
            for (int kk = 0; kk < 4; kk++) {
                ulonglong2 bb =
                    *(const ulonglong2*)&Bs[cur][k4 * 4 + kk][col0];
#pragma unroll
                for (int r = 0; r < 4; r++) {
                    float av = (kk == 0) ? a4[r].x
                             : (kk == 1) ? a4[r].y
                             : (kk == 2) ? a4[r].z : a4[r].w;
                    ull aa = pack2(av);
                    acc[r][0] = fma2(aa, bb.x, acc[r][0]);
                    acc[r][1] = fma2(aa, bb.y, acc[r][1]);
                }
            }
        }
    }
}

// ---------------------------------------------------------------------------
__global__ void k_init(const int* __restrict__ captions) {
    int i = blockIdx.x * blockDim.x + threadIdx.x;
    if (i < B_ * 512) { g_h[i] = 0.f; g_c[i] = 0.f; }
    if (i < B_)
        g_amax[i] = (ull)(0xFFFFFFFFu - (unsigned)captions[i * T_]);
}

__global__ void k_mul() {   // g_av *= g_bv (one-time, folds AmulRow out of hot path)
    int i = blockIdx.x * blockDim.x + threadIdx.x;
    if (i < B_ * 2048) g_av[i] *= g_bv[i];
}

// ---------------------------------------------------------------------------
// k_mm: precompute  C[64,2048] = A[64,K] @ W[4,K,512]
// ---------------------------------------------------------------------------
__global__ void __launch_bounds__(NT)
k_mm(const float* __restrict__ A, int K, const float* __restrict__ W,
     int outSel) {
    const int tid = threadIdx.x;
    const int nBase = blockIdx.x * BN;
    const int g = nBase >> 9, nIn = nBase & 511;

    const float* ap[ACH]; int kcA[ACH];
#pragma unroll
    for (int i = 0; i < ACH; i++) {
        int c = tid + NT * i, row = c >> 3, kc = c & 7;
        kcA[i] = kc * 4;
        ap[i] = A + (size_t)row * K + kc * 4;
    }
    const float* bp[2]; int kkB[2]; bool bok[2];
#pragma unroll
    for (int i = 0; i < 2; i++) {
        int c = tid + NT * i, kk = c >> 3, jc = c & 7;
        kkB[i] = kk; bok[i] = true;
        bp[i] = W + (size_t)g * K * 512 + (size_t)kk * 512 + nIn + jc * 4;
    }
    ull acc[4][2] = {};
    mm_pipe<true, false>(ap, kcA, bp, kkB, bok, 512, K, acc);

    float* C = (outSel == 0) ? g_bx : (outSel == 1) ? g_bh
             : (outSel == 2) ? g_bv : g_av;
    const int row0 = (tid >> 3) << 2, col0 = (tid & 7) << 2;
#pragma unroll
    for (int r = 0; r < 4; r++) {
        float f[4];
        unpack2(acc[r][0], f[0], f[1]);
        unpack2(acc[r][1], f[2], f[3]);
        size_t o = (size_t)(row0 + r) * 2048 + nBase + col0;
#pragma unroll
        for (int c = 0; c < 4; c++) C[o + c] = f[c];
    }
}

// ---------------------------------------------------------------------------
// k_uw: path0: u = (Wa @ embed[cap]) * bx ; path1: w = (Ua @ h) * bh
// ---------------------------------------------------------------------------
__global__ void __launch_bounds__(NT)
k_uw(const float* __restrict__ embed, const float* __restrict__ Wa,
     const float* __restrict__ Ua) {
    const int tid = threadIdx.x;
    const int nBase = blockIdx.x * BN;
    const int g = nBase >> 9, nIn = nBase & 511;
    const int path = blockIdx.y;

    const float* ap[ACH]; int kcA[ACH];
#pragma unroll
    for (int i = 0; i < ACH; i++) {
        int c = tid + NT * i, row = c >> 3, kc = c & 7;
        kcA[i] = kc * 4;
        if (path == 0) {
            unsigned cap = 0xFFFFFFFFu - (unsigned)g_amax[row];
            ap[i] = embed + (size_t)cap * 512 + kc * 4;
        } else {
            ap[i] = g_h + (size_t)row * 512 + kc * 4;
        }
    }
    const float* W = (path == 0) ? Wa : Ua;
    const float* bp[2]; int kkB[2]; bool bok[2];
#pragma unroll
    for (int i = 0; i < 2; i++) {
        int c = tid + NT * i, kk = c >> 3, jc = c & 7;
        kkB[i] = kk; bok[i] = true;
        bp[i] = W + (size_t)g * (512 * 512) + (size_t)kk * 512 + nIn + jc * 4;
    }
    ull acc[4][2] = {};
    mm_pipe<false, false>(ap, kcA, bp, kkB, bok, 512, 512, acc);

    const float* emul = (path == 0) ? g_bx : g_bh;
    float* C          = (path == 0) ? g_u : g_w;
    const int row0 = (tid >> 3) << 2, col0 = (tid & 7) << 2;
#pragma unroll
    for (int r = 0; r < 4; r++) {
        float f[4];
        unpack2(acc[r][0], f[0], f[1]);
        unpack2(acc[r][1], f[2], f[3]);
        size_t o = (size_t)(row0 + r) * 2048 + nBase + col0;
#pragma unroll
        for (int c = 0; c < 4; c++) C[o + c] = f[c] * emul[o + c];
    }
}

// ---------------------------------------------------------------------------
// k_pre: block-diagonal per-gate GEMM.
// mode 0 (grid.y=2): preW = Wc(g) @ u(g) ; preU = Uc(g) @ w(g)
// mode 1 (grid.y=1): preBase = Cc(g) @ (av*bv)(g) + bias   (one-time; g_av
//                    already multiplied by g_bv via k_mul)
// ---------------------------------------------------------------------------
__global__ void __launch_bounds__(NT)
k_pre(const float* __restrict__ W0, const float* __restrict__ W1,
      const float* __restrict__ biasv, int mode) {
    const int tid = threadIdx.x;
    const int nBase = blockIdx.x * BN;
    const int g = nBase >> 9, nIn = nBase & 511;
    const int path = blockIdx.y;

    const float* A; const float* W; const float* ab = nullptr; float* C;
    if (mode == 0) {
        if (path == 0) { A = g_u; W = W0; C = g_preW; }
        else           { A = g_w; W = W1; C = g_preU; }
    } else {
        A = g_av; W = W0; ab = biasv; C = g_preBase;
    }

    const float* ap[ACH]; int kcA[ACH];
#pragma unroll
    for (int i = 0; i < ACH; i++) {
        int c = tid + NT * i, row = c >> 3, kc = c & 7;
        kcA[i] = kc * 4;
        ap[i] = A + (size_t)row * 2048 + g * 512 + kc * 4;
    }
    const float* bp[2]; int kkB[2]; bool bok[2];
#pragma unroll
    for (int i = 0; i < 2; i++) {
        int c = tid + NT * i, kk = c >> 3, jc = c & 7;
        kkB[i] = kk; bok[i] = true;
        bp[i] = W + (size_t)g * (512 * 512) + (size_t)kk * 512 + nIn + jc * 4;
    }
    ull acc[4][2] = {};
    mm_pipe<false, false>(ap, kcA, bp, kkB, bok, 512, 512, acc);

    const int row0 = (tid >> 3) << 2, col0 = (tid & 7) << 2;
#pragma unroll
    for (int r = 0; r < 4; r++) {
        float f[4];
        unpack2(acc[r][0], f[0], f[1]);
        unpack2(acc[r][1], f[2], f[3]);
        size_t o = (size_t)(row0 + r) * 2048 + nBase + col0;
#pragma unroll
        for (int c = 0; c < 4; c++) {
            float v = f[c];
            if (ab) v += ab[nBase + col0 + c];
            C[o + c] = v;
        }
    }
}

// ---------------------------------------------------------------------------
// k_cell: LSTM cell update + reset argmax keys. 64 blocks x 512 threads.
// ---------------------------------------------------------------------------
__global__ void k_cell() {
    int b = blockIdx.x, hh = threadIdx.x;
    int base = b * 2048;
    float pi = g_preW[base + hh]         + g_preU[base + hh]         + g_preBase[base + hh];
    float pf = g_preW[base + 512 + hh]   + g_preU[base + 512 + hh]   + g_preBase[base + 512 + hh];
    float po = g_preW[base + 1024 + hh]  + g_preU[base + 1024 + hh]  + g_preBase[base + 1024 + hh];
    float pg = g_preW[base + 1536 + hh]  + g_preU[base + 1536 + hh]  + g_preBase[base + 1536 + hh];
    float ig = 1.f / (1.f + expf(-pi));
    float fg = 1.f / (1.f + expf(-pf));
    float og = 1.f / (1.f + expf(-po));
    float gg = tanhf(pg);
    int idx = b * 512 + hh;
    float c = fg * g_c[idx] + ig * gg;
    g_c[idx] = c;
    g_h[idx] = og * tanhf(c);
    if (hh == 0) g_amax[b] = 0ull;
}

// ---------------------------------------------------------------------------
// k_out: out = h @ W_last + b_last ; argmax via atomicMax on
// (ord(value)<<32 | ~col) keys — first-index tie-break like jnp.argmax.
// ---------------------------------------------------------------------------
__global__ void __launch_bounds__(NT)
k_out(const float* __restrict__ Wl, const float* __restrict__ bl,
      float* __restrict__ outp) {
    const int tid = threadIdx.x;
    const int nBase = blockIdx.x * BN;
    int nValid = VOCAB_ - nBase;
    if (nValid > BN) nValid = BN;

    const float* ap[ACH]; int kcA[ACH];
#pragma unroll
    for (int i = 0; i < ACH; i++) {
        int c = tid + NT * i, row = c >> 3, kc = c & 7;
        kcA[i] = kc * 4;
        ap[i] = g_h + (size_t)row * 512 + kc * 4;
    }
    const float* bp[2]; int kkB[2]; bool bok[2];
#pragma unroll
    for (int i = 0; i < 2; i++) {
        int c = tid + NT * i, kk = c >> 3, jc = c & 7;
        kkB[i] = kk;
        bok[i] = (jc * 4 + 4) <= nValid;
        bp[i] = Wl + (size_t)kk * VOCAB_ + nBase + jc * 4;
    }
    ull acc[4][2] = {};
    mm_pipe<false, true>(ap, kcA, bp, kkB, bok, VOCAB_, 512, acc);

    const int row0 = (tid >> 3) << 2, col0 = (tid & 7) << 2;
    __shared__ ull sk[64][8];
#pragma unroll
    for (int r = 0; r < 4; r++) {
        int m = row0 + r;
        float f[4];
        unpack2(acc[r][0], f[0], f[1]);
        unpack2(acc[r][1], f[2], f[3]);
        ull best = 0ull;
#pragma unroll
        for (int c = 0; c < 4; c++) {
            int n = nBase + col0 + c;
            if (col0 + c < nValid) {
                float v = f[c] + bl[n];
                outp[(size_t)m * (NSTEPS * VOCAB_) + n] = v;
                ull key = ((ull)fordu(v) << 32) |
                          (ull)(0xFFFFFFFFu - (unsigned)n);
                best = kmax64(best, key);
            }
        }
        sk[m][tid & 7] = best;
    }
    __syncthreads();
    if (tid < 64) {
        ull best = sk[tid][0];
#pragma unroll
        for (int j = 1; j < 8; j++) best = kmax64(best, sk[tid][j]);
        atomicMax(&g_amax[tid], best);
    }
}

// ---------------------------------------------------------------------------
extern "C" void kernel_launch(void* const* d_in, const int* in_sizes, int n_in,
                              void* d_out, int out_size) {
    (void)in_sizes; (void)n_in; (void)out_size;
    const int*   captions = (const int*)d_in[0];
    const float* cnn      = (const float*)d_in[1];
    const float* sem      = (const float*)d_in[2];
    const float* Wa       = (const float*)d_in[3];
    const float* Wb       = (const float*)d_in[4];
    const float* Wc       = (const float*)d_in[5];
    const float* Ca       = (const float*)d_in[6];
    const float* Cb       = (const float*)d_in[7];
    const float* Cc       = (const float*)d_in[8];
    const float* Ua       = (const float*)d_in[9];
    const float* Ub       = (const float*)d_in[10];
    const float* Uc       = (const float*)d_in[11];
    const float* bias     = (const float*)d_in[12];
    const float* embed    = (const float*)d_in[13];
    const float* Wl       = (const float*)d_in[14];
    const float* bl       = (const float*)d_in[15];
    float* out = (float*)d_out;

    k_init<<<128, 256>>>(captions);

    // one-time precompute
    k_mm<<<64, NT>>>(sem, 300, Wb, 0);      // bx
    k_mm<<<64, NT>>>(sem, 300, Ub, 1);      // bh
    k_mm<<<64, NT>>>(sem, 300, Cb, 2);      // bv
    k_mm<<<64, NT>>>(cnn, 2048, Ca, 3);     // av
    k_mul<<<512, 256>>>();                  // av *= bv
    k_pre<<<dim3(64, 1), NT>>>(Cc, Cc, bias, 1);  // preBase = v_feat + bias

    // recurrent steps
    for (int t = 0; t < NSTEPS; ++t) {
        k_uw<<<dim3(64, 2), NT>>>(embed, Wa, Ua);
        k_pre<<<dim3(64, 2), NT>>>(Wc, Uc, nullptr, 0);
        k_cell<<<64, 512>>>();
        k_out<<<313, NT>>>(Wl, bl, out + (size_t)t * VOCAB_);
    }
}